// round 5
// baseline (speedup 1.0000x reference)
#include <cuda_runtime.h>
#include <stdint.h>

// Problem constants
#define BATCH 4
#define SEQ   8192
#define DIM   64
#define NHASH 8
#define NROT  64      // n_buckets/2 : rotation output columns
#define TM    128     // query rows per block
#define NTHREADS 256

// ---------------------------------------------------------------------------
// Standalone copy kernel (only used if harness asks for out-only layout)
// ---------------------------------------------------------------------------
__global__ void copy_v_kernel(const float4* __restrict__ v, float4* __restrict__ out, int n4)
{
    int i = blockIdx.x * blockDim.x + threadIdx.x;
    int stride = gridDim.x * blockDim.x;
    for (; i < n4; i += stride) out[i] = v[i];
}

// packed fp32x2 FMA: d.lo += a.lo*b.lo ; d.hi += a.hi*b.hi  (SASS FFMA2)
__device__ __forceinline__ void ffma2(unsigned long long& d,
                                      unsigned long long a,
                                      unsigned long long b)
{
    asm("fma.rn.f32x2 %0, %1, %2, %0;" : "+l"(d) : "l"(a), "l"(b));
}

// ---------------------------------------------------------------------------
// Hash kernel (+ fused v copy).
// rotated[b,h,t,i] = sum_f qk[b,t,f] * rot[f,h,i];  bucket = signed argmax + h*128
//
// Block: 256 threads computes a 128(t) x 64(i) tile for one (b,h).
// Thread tile: 8 rows x 4 cols, accumulators packed over k-parity (f32x2):
//   acc.lo = sum over even k, acc.hi = sum over odd k, value = lo + hi.
// a-pairs: adjacent k in sQ (LDS.64). b-pairs: adjacent k in TRANSPOSED
// rotation tile sRT[i][k] (LDS.128 -> two u64). XOR chunk swizzle on both
// tiles gives conflict-free (a) / floor-2-phase (b) shared loads.
// ---------------------------------------------------------------------------
__global__ __launch_bounds__(NTHREADS, 2) void hash_kernel(
    const float* __restrict__ qk,
    const float* __restrict__ rot,           // [f=64][h=8][i=64]
    const float4* __restrict__ vin,          // v as float4 (may be ignored)
    float4* __restrict__ vout,               // out tensor as float4 (nullable)
    float* __restrict__ out_buckets)
{
    __shared__ __align__(16) float sRT[64 * 64];   // sRT[i][k], chunk-swizzled
    __shared__ __align__(16) float sQ[TM * 64];    // sQ[t][k],  chunk-swizzled

    const int tid = threadIdx.x;
    const int t0  = blockIdx.x * TM;
    const int h   = blockIdx.y;
    const int b   = blockIdx.z;

    // ---- fused v copy: issue load now, store at the end (latency hidden) ----
    float4 vreg;
    int vidx = 0;
    if (vout) {
        int blin = (blockIdx.z * NHASH + blockIdx.y) * gridDim.x + blockIdx.x;
        vidx = blin * NTHREADS + tid;                 // 2048 blocks * 256 = 524288 float4
        vreg = vin[vidx];
    }

    // ---- load rotation slice for this h, TRANSPOSED to [i][k], swizzled ----
    // Tile is 64(f) x 16 float4(i-chunks) = 1024 float4 -> 4 iters of 256 threads.
    // phys addr of (i,k): i*64 + (((k>>2) ^ (i>>3)) & 15)*4 + (k&3)
    {
        const float* rh = rot + h * NROT;
        #pragma unroll
        for (int it = 0; it < 4; it++) {
            int idx = tid + it * NTHREADS;            // 1024 float4 total
            int f = idx >> 4;                          // k: 0..63
            int j = idx & 15;                          // i-chunk
            float4 rv = *reinterpret_cast<const float4*>(rh + f * (NHASH * NROT) + j * 4);
            float vals[4] = {rv.x, rv.y, rv.z, rv.w};
            #pragma unroll
            for (int e = 0; e < 4; e++) {
                int i = j * 4 + e;
                sRT[i * 64 + (((f >> 2) ^ (i >> 3)) & 15) * 4 + (f & 3)] = vals[e];
            }
        }
    }

    // ---- load q tile: 128 rows x 64, swizzled ----
    // phys addr of (t,k): t*64 + (((k>>2) ^ (t>>3)) & 15)*4 + (k&3)
    {
        const float* qb = qk + ((size_t)b * SEQ + t0) * DIM;
        #pragma unroll
        for (int it = 0; it < 8; it++) {
            int idx = tid + it * NTHREADS;            // 2048 float4 total
            int t = idx >> 4;
            int j = idx & 15;
            float4 val = *reinterpret_cast<const float4*>(qb + t * DIM + j * 4);
            *reinterpret_cast<float4*>(sQ + t * 64 + ((j ^ (t >> 3)) & 15) * 4) = val;
        }
    }
    __syncthreads();

    const int ct = tid & 15;        // col group: cols [ct*4, ct*4+4)
    const int rt = tid >> 4;        // row group: rows [rt*8, rt*8+8)
    const int bswz = ct >> 1;       // == (ct*4+c)>>3 for c<4

    unsigned long long acc[8][4];
    #pragma unroll
    for (int r = 0; r < 8; r++)
        #pragma unroll
        for (int c = 0; c < 4; c++) acc[r][c] = 0ull;

    #pragma unroll
    for (int kc = 0; kc < 16; kc++) {               // k-chunk of 4
        // b: 4 cols x float4 (k..k+3) from transposed tile
        ulonglong2 bv[4];
        const int bchunk = ((kc ^ bswz) & 15) * 4;
        #pragma unroll
        for (int c = 0; c < 4; c++) {
            int i = ct * 4 + c;
            bv[c] = *reinterpret_cast<const ulonglong2*>(sRT + i * 64 + bchunk);
        }
        const int achunk = ((kc ^ rt) & 15) * 4;
        #pragma unroll
        for (int half = 0; half < 2; half++) {
            unsigned long long ap[8];
            #pragma unroll
            for (int r = 0; r < 8; r++)
                ap[r] = *reinterpret_cast<const unsigned long long*>(
                            sQ + (rt * 8 + r) * 64 + achunk + half * 2);
            #pragma unroll
            for (int r = 0; r < 8; r++) {
                #pragma unroll
                for (int c = 0; c < 4; c++) {
                    unsigned long long bb = half ? bv[c].y : bv[c].x;
                    ffma2(acc[r][c], ap[r], bb);
                }
            }
        }
    }

    // ---- signed argmax per row, reduce across the 16 col-group lanes ----
    // argmax over [r_0..r_63, -r_0..-r_63], first occurrence on ties:
    // strict-greater wins; on equal value, smaller index wins.
    #pragma unroll
    for (int r = 0; r < 8; r++) {
        float vals[4];
        #pragma unroll
        for (int c = 0; c < 4; c++) {
            float lo = __uint_as_float((unsigned)(acc[r][c] & 0xffffffffull));
            float hi = __uint_as_float((unsigned)(acc[r][c] >> 32));
            vals[c] = lo + hi;
        }
        float bvv = vals[0];
        int   bi  = ct * 4;
        #pragma unroll
        for (int c = 1; c < 4; c++) {
            int idx = ct * 4 + c;
            if (vals[c] > bvv || (vals[c] == bvv && idx < bi)) { bvv = vals[c]; bi = idx; }
        }
        #pragma unroll
        for (int c = 0; c < 4; c++) {
            float nv = -vals[c]; int idx = ct * 4 + c + 64;
            if (nv > bvv || (nv == bvv && idx < bi)) { bvv = nv; bi = idx; }
        }
        // reduce across the 16 lanes sharing this row group (xor masks stay in-group)
        #pragma unroll
        for (int m = 1; m < 16; m <<= 1) {
            float ov = __shfl_xor_sync(0xffffffffu, bvv, m);
            int   oi = __shfl_xor_sync(0xffffffffu, bi, m);
            if (ov > bvv || (ov == bvv && oi < bi)) { bvv = ov; bi = oi; }
        }
        if (ct == 0) {
            int t = t0 + rt * 8 + r;
            out_buckets[((size_t)b * NHASH + h) * SEQ + t] = (float)(bi + h * 128);
        }
    }

    // ---- store fused v copy ----
    if (vout) vout[vidx] = vreg;
}

// ---------------------------------------------------------------------------
// Launch
// ---------------------------------------------------------------------------
extern "C" void kernel_launch(void* const* d_in, const int* in_sizes, int n_in,
                              void* d_out, int out_size)
{
    const float* qk  = (const float*)d_in[0];   // (4, 8192, 64)
    const float* v   = (const float*)d_in[1];   // (4, 8192, 64)
    const float* rot = (const float*)d_in[2];   // (1, 64, 8, 64)
    float* out = (float*)d_out;

    const int N_OUT = BATCH * SEQ * DIM;        // 2,097,152
    const int N_BKT = BATCH * NHASH * SEQ;      //   262,144

    // Output layout: (out, buckets) flattened in tuple order as float32;
    // branch on out_size so single-output harnesses also work.
    if (out_size == N_OUT) {
        copy_v_kernel<<<1024, 256>>>((const float4*)v, (float4*)out, N_OUT / 4);
        return;
    }

    float4* vout   = nullptr;
    float*  out_b  = out;
    if (out_size != N_BKT) {           // combined (default): out || buckets
        vout  = (float4*)out;
        out_b = out + N_OUT;
    }

    dim3 grid(SEQ / TM, NHASH, BATCH);          // (64, 8, 4) = 2048 blocks
    hash_kernel<<<grid, NTHREADS>>>(qk, rot, (const float4*)v, vout, out_b);
}

// round 6
// speedup vs baseline: 1.1925x; 1.1925x over previous
#include <cuda_runtime.h>
#include <stdint.h>

// Problem constants
#define BATCH 4
#define SEQ   8192
#define DIM   64
#define NHASH 8
#define NROT  64      // n_buckets/2 : rotation output columns
#define TM    128     // query rows per block
#define NTHREADS 128

#define SQ_STRIDE 68  // padded row stride for q tile (float4-aligned, conflict-free w/ kshift)

// ---------------------------------------------------------------------------
// Standalone copy kernel (only used if harness asks for out-only layout)
// ---------------------------------------------------------------------------
__global__ void copy_v_kernel(const float4* __restrict__ v, float4* __restrict__ out, int n4)
{
    int i = blockIdx.x * blockDim.x + threadIdx.x;
    int stride = gridDim.x * blockDim.x;
    for (; i < n4; i += stride) out[i] = v[i];
}

// packed fp32x2 FMA: d.lo += a.lo*b.lo ; d.hi += a.hi*b.hi  (SASS FFMA2)
__device__ __forceinline__ void ffma2(unsigned long long& d,
                                      unsigned long long a,
                                      unsigned long long b)
{
    asm("fma.rn.f32x2 %0, %1, %2, %0;" : "+l"(d) : "l"(a), "l"(b));
}

// duplicate one fp32 into both lanes of a 64-bit pair
__device__ __forceinline__ unsigned long long dup2(float a)
{
    unsigned long long r;
    asm("mov.b64 %0, {%1, %1};" : "=l"(r) : "f"(a));
    return r;
}

// ---------------------------------------------------------------------------
// Hash kernel (+ fused v copy).
// rotated[b,h,t,i] = sum_f qk[b,t,f] * rot[f,h,i];  bucket = signed argmax + h*128
//
// Round-3 memory structure (proven conflict-free, at-floor):
//   128 threads, tile 128(t) x 64(i), thread tile 8x8.
//   ct = tid&7 (cols ct*8..+8), rt = tid>>3 (rows rt*8..+8), per-rt kshift
//   rotation so scalar q loads are conflict-free broadcasts and b LDS.128
//   phases stay contiguous/conflict-free.
// Arithmetic: FFMA2 with accumulators paired over adjacent columns:
//   acc[r][cp].lo = col 2cp, .hi = col 2cp+1. b-pairs come packed for free
//   from k-major sR via LDS.128; a is duplicated via mov.b64 {a,a} (alu pipe).
// Accumulation order per (r,c) is bitwise identical to the scalar round-3
// kernel, so bucket argmax results are unchanged.
// ---------------------------------------------------------------------------
__global__ __launch_bounds__(NTHREADS, 4) void hash_kernel(
    const float* __restrict__ qk,
    const float* __restrict__ rot,           // [f=64][h=8][i=64]
    const float4* __restrict__ vin,          // v as float4 (may be ignored)
    float4* __restrict__ vout,               // out tensor as float4 (nullable)
    float* __restrict__ out_buckets)
{
    __shared__ __align__(16) float sR[64 * 64];           // sR[k][i], k-major
    __shared__ __align__(16) float sQ[TM * SQ_STRIDE];    // sQ[t][k]

    const int tid = threadIdx.x;
    const int t0  = blockIdx.x * TM;
    const int h   = blockIdx.y;
    const int b   = blockIdx.z;

    // ---- load rotation slice for this h: 64x64 floats (1024 float4) ----
    #pragma unroll
    for (int i = tid; i < 1024; i += NTHREADS) {
        int f = i >> 4, j = i & 15;
        float4 val = *reinterpret_cast<const float4*>(rot + f * (NHASH * NROT) + h * NROT + j * 4);
        *reinterpret_cast<float4*>(sR + f * 64 + j * 4) = val;
    }

    // ---- load q tile: 128 rows x 64 (2048 float4) ----
    const float* qb = qk + ((size_t)b * SEQ + t0) * DIM;
    #pragma unroll
    for (int i = tid; i < 2048; i += NTHREADS) {
        int t = i >> 4, j = i & 15;
        float4 val = *reinterpret_cast<const float4*>(qb + t * DIM + j * 4);
        *reinterpret_cast<float4*>(sQ + t * SQ_STRIDE + j * 4) = val;
    }
    __syncthreads();

    const int ct = tid & 7;        // col group: cols [ct*8, ct*8+8)
    const int rt = tid >> 3;       // row group: rows [rt*8, rt*8+8)
    const int kshift = (rt & 7) * 8;

    unsigned long long acc[8][4];  // [row][col-pair] : lo=col 2cp, hi=col 2cp+1
    #pragma unroll
    for (int r = 0; r < 8; r++)
        #pragma unroll
        for (int c = 0; c < 4; c++) acc[r][c] = 0ull;

    #pragma unroll 8
    for (int kk = 0; kk < 64; kk++) {
        const int k = (kk + kshift) & 63;
        // a: 8 scalar broadcasts, duplicated into f32x2 pairs (alu-pipe MOVs)
        unsigned long long ap[8];
        #pragma unroll
        for (int r = 0; r < 8; r++)
            ap[r] = dup2(sQ[(rt * 8 + r) * SQ_STRIDE + k]);
        // b: 8 cols = 4 natural f32x2 pairs via two LDS.128
        ulonglong2 b0 = *reinterpret_cast<const ulonglong2*>(sR + k * 64 + ct * 8);
        unsigned long long bp[4] = {b0.x, b0.y, 0, 0};
        ulonglong2 b1 = *reinterpret_cast<const ulonglong2*>(sR + k * 64 + ct * 8 + 4);
        bp[2] = b1.x; bp[3] = b1.y;
        #pragma unroll
        for (int r = 0; r < 8; r++)
            #pragma unroll
            for (int c = 0; c < 4; c++)
                ffma2(acc[r][c], ap[r], bp[c]);
    }

    // ---- signed argmax per row, reduce across the 8 col-group lanes ----
    // argmax over [r_0..r_63, -r_0..-r_63], first occurrence on ties:
    // strict-greater wins; on equal value, smaller index wins.
    #pragma unroll
    for (int r = 0; r < 8; r++) {
        float vals[8];
        #pragma unroll
        for (int c = 0; c < 4; c++) {
            vals[2 * c]     = __uint_as_float((unsigned)(acc[r][c] & 0xffffffffull));
            vals[2 * c + 1] = __uint_as_float((unsigned)(acc[r][c] >> 32));
        }
        float bvv = vals[0];
        int   bi  = ct * 8;
        #pragma unroll
        for (int c = 1; c < 8; c++) {
            int idx = ct * 8 + c;
            if (vals[c] > bvv || (vals[c] == bvv && idx < bi)) { bvv = vals[c]; bi = idx; }
        }
        #pragma unroll
        for (int c = 0; c < 8; c++) {
            float nv = -vals[c]; int idx = ct * 8 + c + 64;
            if (nv > bvv || (nv == bvv && idx < bi)) { bvv = nv; bi = idx; }
        }
        // reduce across 8 lanes sharing this row group (xor masks stay in-group)
        #pragma unroll
        for (int m = 1; m < 8; m <<= 1) {
            float ov = __shfl_xor_sync(0xffffffffu, bvv, m);
            int   oi = __shfl_xor_sync(0xffffffffu, bi, m);
            if (ov > bvv || (ov == bvv && oi < bi)) { bvv = ov; bi = oi; }
        }
        if (ct == 0) {
            int t = t0 + rt * 8 + r;
            out_buckets[((size_t)b * NHASH + h) * SEQ + t] = (float)(bi + h * 128);
        }
    }

    // ---- fused v copy (2 float4 per thread; latency hidden across blocks) ----
    if (vout) {
        int blin = (b * NHASH + h) * gridDim.x + blockIdx.x;
        int base = blin * 256 + tid;               // 2048 blocks * 256 f4 = 524288
        vout[base]       = vin[base];
        vout[base + 128] = vin[base + 128];
    }
}

// ---------------------------------------------------------------------------
// Launch
// ---------------------------------------------------------------------------
extern "C" void kernel_launch(void* const* d_in, const int* in_sizes, int n_in,
                              void* d_out, int out_size)
{
    const float* qk  = (const float*)d_in[0];   // (4, 8192, 64)
    const float* v   = (const float*)d_in[1];   // (4, 8192, 64)
    const float* rot = (const float*)d_in[2];   // (1, 64, 8, 64)
    float* out = (float*)d_out;

    const int N_OUT = BATCH * SEQ * DIM;        // 2,097,152
    const int N_BKT = BATCH * NHASH * SEQ;      //   262,144

    // Output layout: (out, buckets) flattened in tuple order as float32;
    // branch on out_size so single-output harnesses also work.
    if (out_size == N_OUT) {
        copy_v_kernel<<<1024, 256>>>((const float4*)v, (float4*)out, N_OUT / 4);
        return;
    }

    float4* vout   = nullptr;
    float*  out_b  = out;
    if (out_size != N_BKT) {           // combined (default): out || buckets
        vout  = (float4*)out;
        out_b = out + N_OUT;
    }

    dim3 grid(SEQ / TM, NHASH, BATCH);          // (64, 8, 4) = 2048 blocks
    hash_kernel<<<grid, NTHREADS>>>(qk, rot, (const float4*)v, vout, out_b);
}